// round 11
// baseline (speedup 1.0000x reference)
#include <cuda_runtime.h>
#include <cstdint>

// Bit-packed binary volume: z packed 32 voxels/uint32.
// Row = (n, bx, by), bx,by in [0,164) (guard ring + padded 162), 6 words/row.
// bit index bz = padded z + 1;  buffer coord b = padded p + 1 = image ix + 2.
#define NR    164
#define ROWW  6
#define NROWW (NR*NR*ROWW)        // words per batch item: 161,376
#define NWORDS (2*NROWW)          // 322,752 words = 1.29 MB

#define NBLK  296
#define NTHR  512
#define TTOT  (NBLK*NTHR)         // 151,552 threads

__device__ __align__(16) uint32_t g_bits[NWORDS];
__device__ __align__(16) uint32_t g_endb[NWORDS];   // "n26sum >= 2" mask
__device__ uint32_t g_bar_count;                    // zero-init; returns to 0 each run
__device__ uint32_t g_bar_gen;                      // monotonically increasing

// ---------------- grid-wide software barrier --------------------------------
__device__ __forceinline__ void gridbar(uint32_t &gen){
  __syncthreads();
  if (threadIdx.x == 0){
    __threadfence();                                  // publish this block's stores
    uint32_t target = gen + 1u;
    if (atomicAdd(&g_bar_count, 1u) == (uint32_t)(NBLK - 1)){
      g_bar_count = 0u;                               // reset for next barrier
      __threadfence();                                // order reset before release
      atomicExch(&g_bar_gen, target);                 // release
    } else {
      while (*(volatile uint32_t*)&g_bar_gen != target) { }
    }
    gen = target;
    __threadfence();                                  // order release before our next reads
  }
  __syncthreads();
}

// ---------------- threefry2x32 (JAX), partitionable 32-bit combine ----------
__device__ __forceinline__ uint32_t rotl32(uint32_t x, int d){ return (x<<d)|(x>>(32-d)); }

__device__ __forceinline__ uint32_t threefry_bits(uint32_t x0, uint32_t x1){
  const uint32_t k0 = 0u, k1 = 42u;
  const uint32_t k2 = k0 ^ k1 ^ 0x1BD11BDAu;
  x0 += k0; x1 += k1;
#define TF_R(r) { x0 += x1; x1 = rotl32(x1,(r)); x1 ^= x0; }
  TF_R(13) TF_R(15) TF_R(26) TF_R(6)
  x0 += k1; x1 += k2 + 1u;
  TF_R(17) TF_R(29) TF_R(16) TF_R(24)
  x0 += k2; x1 += k0 + 2u;
  TF_R(13) TF_R(15) TF_R(26) TF_R(6)
  x0 += k0; x1 += k1 + 3u;
  TF_R(17) TF_R(29) TF_R(16) TF_R(24)
  x0 += k1; x1 += k2 + 4u;
  TF_R(13) TF_R(15) TF_R(26) TF_R(6)
  x0 += k2; x1 += k0 + 5u;
#undef TF_R
  return x0 ^ x1;
}

#define ACC(x) { ge2 |= ge1 & (x); ge1 |= (x); }

// Load the 27 z-aligned neighbor bit-vectors for word w of row rowc (L2 reads).
#define LOAD_NBRS(B, rowc, w)                                         \
  uint32_t A0[3][3], Am[3][3], Ap[3][3];                              \
  _Pragma("unroll")                                                   \
  for (int dx=0; dx<3; dx++){                                         \
    _Pragma("unroll")                                                 \
    for (int dy=0; dy<3; dy++){                                       \
      const uint32_t* r = (B) + (size_t)((rowc) + (dx-1)*NR + (dy-1))*ROWW; \
      uint32_t c  = __ldcg(r + (w));                                  \
      uint32_t pv = (w)      ? __ldcg(r + (w) - 1) : 0u;              \
      uint32_t nx = ((w)<5)  ? __ldcg(r + (w) + 1) : 0u;              \
      A0[dx][dy] = c;                                                 \
      Am[dx][dy] = __funnelshift_l(pv, c, 1);  /* bit z = src z-1 */  \
      Ap[dx][dy] = __funnelshift_r(c, nx, 1);  /* bit z = src z+1 */  \
    }                                                                 \
  }

// ---------------- the whole pipeline in one persistent kernel ----------------
__global__ __launch_bounds__(NTHR, 2) void k_all(const float* __restrict__ img,
                                                 float* __restrict__ out){
  const uint32_t tid = blockIdx.x*NTHR + threadIdx.x;
  uint32_t gen = 0u;
  if (threadIdx.x == 0) gen = *(volatile uint32_t*)&g_bar_gen;

  // ---- phase: zero the packed volume ----
  for (uint32_t i = tid; i < NWORDS/4; i += TTOT)
    reinterpret_cast<uint4*>(g_bits)[i] = make_uint4(0u,0u,0u,0u);
  gridbar(gen);

  // ---- phase: Gumbel-sigmoid binarization (bit-exact, ballot-packed) ----
  {
    const uint32_t lane = threadIdx.x & 31u;
    const uint32_t warp = tid >> 5;
    const uint32_t WTOT = TTOT/32;
    for (uint32_t wt = warp; wt < 314928u; wt += WTOT){   // 2*162*162*6 warp tasks
      uint32_t w  = wt % 6u;   uint32_t r  = wt / 6u;
      uint32_t py = r % 162u;  uint32_t r2 = r / 162u;
      uint32_t px = r2 % 162u; uint32_t n  = r2 / 162u;
      int pz = (int)(w*32u + lane) - 1;

      uint32_t hard = 0u;
      if (pz >= 0 && pz < 162){
        uint32_t lin = ((uint32_t)(((n*162u + px)*162u) + py))*162u + (uint32_t)pz;
        uint32_t bits = threefry_bits(0u, lin);

        const float minv  = (float)1e-8;
        const float maxv  = (float)(1.0 - 1e-8);    // rounds to 1.0f
        const float range = maxv - minv;            // 1.0f

        float fl = __uint_as_float((bits >> 9) | 0x3f800000u) - 1.0f;
        float u  = fmaxf(minv, __fadd_rn(__fmul_rn(fl, range), minv));
        float noise = __fsub_rn(logf(u), log1pf(-u));

        float p = 0.0f;
        if (px>=1 && px<=160 && py>=1 && py<=160 && pz>=1 && pz<=160)
          p = img[ (((n*160u) + (px-1))*160u + (py-1))*160u + (uint32_t)(pz-1) ];

        float a = __fadd_rn(p, 1e-8f);
        float b = __fadd_rn(__fsub_rn(1.0f, p), 1e-8f);
        float z = __fadd_rn(logf(__fdiv_rn(a, b)), __fmul_rn(noise, 0.33f));
        float soft = __fdiv_rn(1.0f, __fadd_rn(1.0f, expf(-z)));
        hard = (soft > 0.5f) ? 1u : 0u;
      }
      uint32_t wbits = __ballot_sync(0xffffffffu, hard);
      if (lane == 0)
        g_bits[ ((size_t)((n*NR + (px+1))*NR) + (py+1))*ROWW + w ] = wbits;
    }
  }
  gridbar(gen);

  // ---- 5 thinning iterations ----
  const int offx[8] = {0,1,0,1,0,1,0,1};
  const int offy[8] = {0,0,1,1,0,0,1,1};
  const int offz[8] = {0,0,0,0,1,1,1,1};

  #pragma unroll 1
  for (int it = 0; it < 5; it++){
    // endpoint snapshot: g_endb = mask of "26-neighborhood sum >= 2"
    for (uint32_t t = tid; t < 307200u; t += TTOT){   // 2*160*160*6
      uint32_t w  = t % 6u;        uint32_t r  = t / 6u;
      uint32_t by = 2u + r % 160u; uint32_t r2 = r / 160u;
      uint32_t bx = 2u + r2 % 160u; uint32_t n = r2 / 160u;
      const uint32_t* B = g_bits + (size_t)n*NROWW;
      uint32_t rowc = bx*NR + by;
      uint32_t ge2out = 0u;
      uint32_t C0 = __ldcg(B + (size_t)rowc*ROWW + w);
      if (C0){
        LOAD_NBRS(B, rowc, w);
        uint32_t ge1 = 0u, ge2 = 0u;
        #pragma unroll
        for (int dx=0; dx<3; dx++)
          #pragma unroll
          for (int dy=0; dy<3; dy++){
            if (!(dx==1 && dy==1)) ACC(A0[dx][dy]);
            ACC(Am[dx][dy]); ACC(Ap[dx][dy]);
          }
        ge2out = ge2;
      }
      g_endb[(size_t)n*NROWW + (size_t)rowc*ROWW + w] = ge2out;
    }
    gridbar(gen);

    #pragma unroll 1
    for (int s = 0; s < 8; s++){
      int bx0 = 3 - offx[s];
      int by0 = 3 - offy[s];
      int bz0 = 3 - offz[s];
      uint32_t pmask = (bz0 & 1) ? 0xAAAAAAAAu : 0x55555555u;

      for (uint32_t t = tid; t < 76800u; t += TTOT){  // 2*80*80*6
        uint32_t w  = t % 6u;   uint32_t r  = t / 6u;
        uint32_t iy = r % 80u;  uint32_t r2 = r / 80u;
        uint32_t ix = r2 % 80u; uint32_t n  = r2 / 80u;
        int bx = bx0 + 2*(int)ix, by = by0 + 2*(int)iy;
        uint32_t* V = g_bits + (size_t)n*NROWW;
        uint32_t rowc = (uint32_t)bx*NR + (uint32_t)by;

        uint32_t C0 = __ldcg(V + (size_t)rowc*ROWW + w);
        if (!C0) continue;

        LOAD_NBRS(V, rowc, w);
        uint32_t C = A0[1][1];
        uint32_t fxm=A0[0][1], fxp=A0[2][1], fym=A0[1][0], fyp=A0[1][2];
        uint32_t fzm=Am[1][1], fzp=Ap[1][1];

        // face-neighbor count via CSA; n6z = 6 - faceSum
        uint32_t s1 = fxm ^ fxp ^ fym,  c1 = (fxm & fxp) | (fym & (fxm ^ fxp));
        uint32_t s2 = fyp ^ fzm ^ fzp,  c2 = (fyp & fzm) | (fzp & (fyp ^ fzm));
        uint32_t b0 = s1 ^ s2,          hh = s1 & s2;
        uint32_t b1 = c1 ^ c2 ^ hh,     b2 = (c1 & c2) | (hh & (c1 ^ c2));
        uint32_t n6eq5 = b0 & ~b1 & b2;          // n6z == 1
        uint32_t n6le4 = ~(b2 & (b1 | b0));      // n6z >= 2

        // exactly-one over 18-set, then extend by 8 corners -> 26-set
        uint32_t ge1 = fxm | fxp, ge2 = fxm & fxp;
        ACC(fym) ACC(fyp) ACC(fzm) ACC(fzp)
        ACC(A0[0][0]) ACC(A0[0][2]) ACC(A0[2][0]) ACC(A0[2][2])
        ACC(Am[0][1]) ACC(Am[2][1]) ACC(Am[1][0]) ACC(Am[1][2])
        ACC(Ap[0][1]) ACC(Ap[2][1]) ACC(Ap[1][0]) ACC(Ap[1][2])
        uint32_t n18eq1 = ge1 & ~ge2;
        ACC(Am[0][0]) ACC(Am[0][2]) ACC(Am[2][0]) ACC(Am[2][2])
        ACC(Ap[0][0]) ACC(Ap[0][2]) ACC(Ap[2][0]) ACC(Ap[2][2])
        uint32_t n26eq1 = ge1 & ~ge2;

        // b26: corner set with its 6 same-octant face/edge neighbors all clear
        uint32_t anyB = 0u;
#define OCT(AS, sx, sy) {                                                  \
        uint32_t o6 = A0[sx][sy] | AS[sx][1] | A0[sx][1]                   \
                    | AS[1][sy] | A0[1][sy] | AS[1][1];                    \
        anyB |= AS[sx][sy] & ~o6; }
        OCT(Am,0,0) OCT(Am,0,2) OCT(Am,2,0) OCT(Am,2,2)
        OCT(Ap,0,0) OCT(Ap,0,2) OCT(Ap,2,0) OCT(Ap,2,2)
#undef OCT

        // a6: face clear with its 4 in-plane edge neighbors all set
        uint32_t anyA =
          (~fxm & A0[0][0] & A0[0][2] & Am[0][1] & Ap[0][1]) |
          (~fxp & A0[2][0] & A0[2][2] & Am[2][1] & Ap[2][1]) |
          (~fym & A0[0][0] & A0[2][0] & Am[1][0] & Ap[1][0]) |
          (~fyp & A0[0][2] & A0[2][2] & Am[1][2] & Ap[1][2]) |
          (~fzm & Am[0][1] & Am[2][1] & Am[1][0] & Am[1][2]) |
          (~fzp & Ap[0][1] & Ap[2][1] & Ap[1][0] & Ap[1][2]);

        uint32_t simple = n6eq5 | n26eq1 | (n18eq1 & ~anyB) | (n6le4 & ~anyA & ~anyB);

        uint32_t wmask = (w==0u) ? 0xFFFFFFFCu : ((w==5u) ? 0x00000003u : 0xFFFFFFFFu);
        uint32_t endg2 = __ldcg(g_endb + (size_t)n*NROWW + (size_t)rowc*ROWW + w);
        uint32_t del   = simple & C & endg2 & wmask & pmask;
        V[(size_t)rowc*ROWW + w] = C & ~del;
      }
      gridbar(gen);
    }
  }

  // ---- phase: output (coalesced float4 stores) ----
  for (uint32_t i = tid; i < 2048000u; i += TTOT){   // 2*160*160*40 float4s
    uint32_t q = i % 40u;   uint32_t r  = i / 40u;
    uint32_t y = r % 160u;  uint32_t r2 = r / 160u;
    uint32_t x = r2 % 160u; uint32_t n  = r2 / 160u;
    const uint32_t* row = g_bits + (size_t)n*NROWW + (size_t)((x+2)*NR + (y+2))*ROWW;
    int bz0 = 4*(int)q + 2;
    int w0 = bz0 >> 5, sh = bz0 & 31;
    uint32_t lo = __ldcg(row + w0);
    uint32_t hi = (w0 < 5) ? __ldcg(row + w0 + 1) : 0u;
    uint32_t b4 = __funnelshift_r(lo, hi, (uint32_t)sh);
    float4 v;
    v.x = (float)( b4        & 1u);
    v.y = (float)((b4 >> 1)  & 1u);
    v.z = (float)((b4 >> 2)  & 1u);
    v.w = (float)((b4 >> 3)  & 1u);
    reinterpret_cast<float4*>(out)[i] = v;
  }
}

// ---------------- launch -----------------------------------------------------
extern "C" void kernel_launch(void* const* d_in, const int* in_sizes, int n_in,
                              void* d_out, int out_size){
  (void)in_sizes; (void)n_in; (void)out_size;
  const float* img = (const float*)d_in[0];
  float* out = (float*)d_out;
  k_all<<<NBLK, NTHR>>>(img, out);
}

// round 14
// speedup vs baseline: 1.0473x; 1.0473x over previous
#include <cuda_runtime.h>
#include <cstdint>

// Bit-packed binary volume: z packed 32 voxels/uint32.
// Row = (n, bx, by), bx,by in [0,164) (guard ring + padded 162), 6 words/row.
// bit index bz = padded z + 1;  buffer coord b = padded p + 1 = image ix + 2.
#define NR    164
#define ROWW  6
#define NROWW (NR*NR*ROWW)        // words per batch item: 161,376

#define NHB   148                 // blocks per half (one batch item)
#define NBLK  (2*NHB)
#define NTHR  512
#define HT    (NHB*NTHR)          // threads per half: 75,776

__device__ __align__(16) uint32_t g_bits[2*NROWW];
__device__ __align__(16) uint32_t g_endb[2*NROWW];   // "n26sum >= 2" mask
__device__ uint32_t g_cnt[2];                        // returns to 0 each barrier
__device__ uint32_t g_gen[2];                        // monotone generation

// ---------------- per-half grid barrier --------------------------------------
// __threadfence() is gpu-scope -> ptxas emits CCTL.IVALL, flushing this SM's
// L1D. All of this block's pre-barrier reads complete before the fence
// (__syncthreads), and all resident blocks are parked at their barriers before
// any release, so post-barrier plain LDGs are coherent.
__device__ __forceinline__ void gridbar(int n, uint32_t &gen){
  __syncthreads();
  if (threadIdx.x == 0){
    __threadfence();
    uint32_t target = gen + 1u;
    if (atomicAdd(&g_cnt[n], 1u) == (uint32_t)(NHB - 1)){
      g_cnt[n] = 0u;
      __threadfence();
      atomicExch(&g_gen[n], target);
    } else {
      while (*(volatile uint32_t*)&g_gen[n] != target) { }
    }
    gen = target;
    __threadfence();
  }
  __syncthreads();
}

// ---------------- threefry2x32 (JAX), partitionable 32-bit combine ----------
__device__ __forceinline__ uint32_t rotl32(uint32_t x, int d){ return (x<<d)|(x>>(32-d)); }

__device__ __forceinline__ uint32_t threefry_bits(uint32_t x0, uint32_t x1){
  const uint32_t k0 = 0u, k1 = 42u;
  const uint32_t k2 = k0 ^ k1 ^ 0x1BD11BDAu;
  x0 += k0; x1 += k1;
#define TF_R(r) { x0 += x1; x1 = rotl32(x1,(r)); x1 ^= x0; }
  TF_R(13) TF_R(15) TF_R(26) TF_R(6)
  x0 += k1; x1 += k2 + 1u;
  TF_R(17) TF_R(29) TF_R(16) TF_R(24)
  x0 += k2; x1 += k0 + 2u;
  TF_R(13) TF_R(15) TF_R(26) TF_R(6)
  x0 += k0; x1 += k1 + 3u;
  TF_R(17) TF_R(29) TF_R(16) TF_R(24)
  x0 += k1; x1 += k2 + 4u;
  TF_R(13) TF_R(15) TF_R(26) TF_R(6)
  x0 += k2; x1 += k0 + 5u;
#undef TF_R
  return x0 ^ x1;
}

#define ACC(x) { ge2 |= ge1 & (x); ge1 |= (x); }

// Load the 27 z-aligned neighbor bit-vectors (plain LDG -> L1-cached; coherent
// across phases via the barrier's CCTL.IVALL).
#define LOAD_NBRS(B, rowc, w)                                         \
  uint32_t A0[3][3], Am[3][3], Ap[3][3];                              \
  _Pragma("unroll")                                                   \
  for (int dx=0; dx<3; dx++){                                         \
    _Pragma("unroll")                                                 \
    for (int dy=0; dy<3; dy++){                                       \
      const uint32_t* r = (B) + (size_t)((rowc) + (dx-1)*NR + (dy-1))*ROWW; \
      uint32_t c  = r[w];                                             \
      uint32_t pv = (w)      ? r[(w)-1] : 0u;                         \
      uint32_t nx = ((w)<5)  ? r[(w)+1] : 0u;                         \
      A0[dx][dy] = c;                                                 \
      Am[dx][dy] = __funnelshift_l(pv, c, 1);  /* bit z = src z-1 */  \
      Ap[dx][dy] = __funnelshift_r(c, nx, 1);  /* bit z = src z+1 */  \
    }                                                                 \
  }

// ---------------- the whole pipeline, one persistent kernel ------------------
__global__ __launch_bounds__(NTHR, 2) void k_all(const float* __restrict__ img,
                                                 float* __restrict__ out){
  const int n  = blockIdx.x / NHB;           // batch item (independent volume)
  const int hb = blockIdx.x % NHB;
  const uint32_t htid = (uint32_t)hb*NTHR + threadIdx.x;
  uint32_t* __restrict__ VOL = g_bits + (size_t)n*NROWW;
  uint32_t* __restrict__ END = g_endb + (size_t)n*NROWW;

  uint32_t gen = 0u;
  if (threadIdx.x == 0) gen = *(volatile uint32_t*)&g_gen[n];

  // ---- phase: zero this half's packed volume ----
  for (uint32_t i = htid; i < NROWW/4; i += HT)
    reinterpret_cast<uint4*>(VOL)[i] = make_uint4(0u,0u,0u,0u);
  gridbar(n, gen);

  // ---- phase: Gumbel-sigmoid binarization (bit-exact), interior only ----
  // Padded boundary voxels are provably always 0 (z <= -18.42+0.33*18.42 < 0),
  // so we only compute px,py,pz in [1,161) and leave the rest zeroed.
  {
    const uint32_t lane = threadIdx.x & 31u;
    const uint32_t warp = htid >> 5;
    for (uint32_t wt = warp; wt < 153600u; wt += HT/32){   // 160*160*6 warp tasks
      uint32_t w  = wt % 6u;   uint32_t r = wt / 6u;
      uint32_t py = 1u + r % 160u;
      uint32_t px = 1u + r / 160u;
      int pz = (int)(w*32u + lane) - 1;

      uint32_t hard = 0u;
      if (pz >= 1 && pz <= 160){
        uint32_t lin = ((uint32_t)((((uint32_t)n*162u + px)*162u) + py))*162u + (uint32_t)pz;
        uint32_t bits = threefry_bits(0u, lin);

        const float minv  = (float)1e-8;
        const float maxv  = (float)(1.0 - 1e-8);    // rounds to 1.0f
        const float range = maxv - minv;            // 1.0f

        float fl = __uint_as_float((bits >> 9) | 0x3f800000u) - 1.0f;
        float u  = fmaxf(minv, __fadd_rn(__fmul_rn(fl, range), minv));
        float noise = __fsub_rn(logf(u), log1pf(-u));

        float p = img[ ((((uint32_t)n*160u) + (px-1))*160u + (py-1))*160u + (uint32_t)(pz-1) ];

        float a = __fadd_rn(p, 1e-8f);
        float b = __fadd_rn(__fsub_rn(1.0f, p), 1e-8f);
        float z = __fadd_rn(logf(__fdiv_rn(a, b)), __fmul_rn(noise, 0.33f));
        // (fdiv(1, 1+e) > 0.5)  <=>  (fadd(1,e) < 2.0f)   [exact, NaN-consistent]
        float w1 = __fadd_rn(1.0f, expf(-z));
        hard = (w1 < 2.0f) ? 1u : 0u;
      }
      uint32_t wbits = __ballot_sync(0xffffffffu, hard);
      if (lane == 0)
        VOL[ ((size_t)(px+1)*NR + (py+1))*ROWW + w ] = wbits;
    }
  }
  gridbar(n, gen);

  // ---- 5 thinning iterations ----
  #pragma unroll 1
  for (int it = 0; it < 5; it++){
    // endpoint snapshot: END = mask of "26-neighborhood sum >= 2".
    // Skip empty words: a stale END word is only consumed when the subfield
    // center word is nonzero, which implies it was nonzero (and written) here.
    for (uint32_t t = htid; t < 153600u; t += HT){   // 160*160*6
      uint32_t w  = t % 6u;        uint32_t r = t / 6u;
      uint32_t by = 2u + r % 160u;
      uint32_t bx = 2u + r / 160u;
      uint32_t rowc = bx*NR + by;
      uint32_t C0 = VOL[(size_t)rowc*ROWW + w];
      if (!C0) continue;
      LOAD_NBRS(VOL, rowc, w);
      uint32_t ge1 = 0u, ge2 = 0u;
      #pragma unroll
      for (int dx=0; dx<3; dx++)
        #pragma unroll
        for (int dy=0; dy<3; dy++){
          if (!(dx==1 && dy==1)) ACC(A0[dx][dy]);
          ACC(Am[dx][dy]); ACC(Ap[dx][dy]);
        }
      END[(size_t)rowc*ROWW + w] = ge2;
    }
    gridbar(n, gen);

    #pragma unroll 1
    for (int s = 0; s < 8; s++){
      int xo = s & 1, yo = (s >> 1) & 1, zo = s >> 2;
      int bx0 = 3 - xo;
      int by0 = 3 - yo;
      uint32_t pmask = ((3 - zo) & 1) ? 0xAAAAAAAAu : 0x55555555u;

      for (uint32_t t = htid; t < 38400u; t += HT){  // 80*80*6
        uint32_t w  = t % 6u;   uint32_t r = t / 6u;
        uint32_t iy = r % 80u;
        uint32_t ix = r / 80u;
        int bx = bx0 + 2*(int)ix, by = by0 + 2*(int)iy;
        uint32_t rowc = (uint32_t)bx*NR + (uint32_t)by;

        uint32_t C0 = VOL[(size_t)rowc*ROWW + w];
        if (!C0) continue;

        LOAD_NBRS(VOL, rowc, w);
        uint32_t C = A0[1][1];
        uint32_t fxm=A0[0][1], fxp=A0[2][1], fym=A0[1][0], fyp=A0[1][2];
        uint32_t fzm=Am[1][1], fzp=Ap[1][1];

        // face-neighbor count via CSA; n6z = 6 - faceSum
        uint32_t s1 = fxm ^ fxp ^ fym,  c1 = (fxm & fxp) | (fym & (fxm ^ fxp));
        uint32_t s2 = fyp ^ fzm ^ fzp,  c2 = (fyp & fzm) | (fzp & (fyp ^ fzm));
        uint32_t b0 = s1 ^ s2,          hh = s1 & s2;
        uint32_t b1 = c1 ^ c2 ^ hh,     b2 = (c1 & c2) | (hh & (c1 ^ c2));
        uint32_t n6eq5 = b0 & ~b1 & b2;          // n6z == 1
        uint32_t n6le4 = ~(b2 & (b1 | b0));      // n6z >= 2

        // exactly-one over 18-set, then extend by 8 corners -> 26-set
        uint32_t ge1 = fxm | fxp, ge2 = fxm & fxp;
        ACC(fym) ACC(fyp) ACC(fzm) ACC(fzp)
        ACC(A0[0][0]) ACC(A0[0][2]) ACC(A0[2][0]) ACC(A0[2][2])
        ACC(Am[0][1]) ACC(Am[2][1]) ACC(Am[1][0]) ACC(Am[1][2])
        ACC(Ap[0][1]) ACC(Ap[2][1]) ACC(Ap[1][0]) ACC(Ap[1][2])
        uint32_t n18eq1 = ge1 & ~ge2;
        ACC(Am[0][0]) ACC(Am[0][2]) ACC(Am[2][0]) ACC(Am[2][2])
        ACC(Ap[0][0]) ACC(Ap[0][2]) ACC(Ap[2][0]) ACC(Ap[2][2])
        uint32_t n26eq1 = ge1 & ~ge2;

        // b26: corner set with its 6 same-octant face/edge neighbors all clear
        uint32_t anyB = 0u;
#define OCT(AS, sx, sy) {                                                  \
        uint32_t o6 = A0[sx][sy] | AS[sx][1] | A0[sx][1]                   \
                    | AS[1][sy] | A0[1][sy] | AS[1][1];                    \
        anyB |= AS[sx][sy] & ~o6; }
        OCT(Am,0,0) OCT(Am,0,2) OCT(Am,2,0) OCT(Am,2,2)
        OCT(Ap,0,0) OCT(Ap,0,2) OCT(Ap,2,0) OCT(Ap,2,2)
#undef OCT

        // a6: face clear with its 4 in-plane edge neighbors all set
        uint32_t anyA =
          (~fxm & A0[0][0] & A0[0][2] & Am[0][1] & Ap[0][1]) |
          (~fxp & A0[2][0] & A0[2][2] & Am[2][1] & Ap[2][1]) |
          (~fym & A0[0][0] & A0[2][0] & Am[1][0] & Ap[1][0]) |
          (~fyp & A0[0][2] & A0[2][2] & Am[1][2] & Ap[1][2]) |
          (~fzm & Am[0][1] & Am[2][1] & Am[1][0] & Am[1][2]) |
          (~fzp & Ap[0][1] & Ap[2][1] & Ap[1][0] & Ap[1][2]);

        uint32_t simple = n6eq5 | n26eq1 | (n18eq1 & ~anyB) | (n6le4 & ~anyA & ~anyB);

        uint32_t wmask = (w==0u) ? 0xFFFFFFFCu : ((w==5u) ? 0x00000003u : 0xFFFFFFFFu);
        uint32_t endg2 = END[(size_t)rowc*ROWW + w];   // NOT-endpoint mask
        uint32_t del   = simple & C & endg2 & wmask & pmask;
        VOL[(size_t)rowc*ROWW + w] = C & ~del;
      }
      gridbar(n, gen);
    }
  }

  // ---- phase: output (coalesced float4 stores) ----
  for (uint32_t i = htid; i < 1024000u; i += HT){    // 160*160*40 float4s
    uint32_t q = i % 40u;   uint32_t r = i / 40u;
    uint32_t y = r % 160u;
    uint32_t x = r / 160u;
    const uint32_t* row = VOL + (size_t)((x+2)*NR + (y+2))*ROWW;
    int bz0 = 4*(int)q + 2;
    int w0 = bz0 >> 5, sh = bz0 & 31;
    uint32_t lo = row[w0];
    uint32_t hi = row[w0 + 1];                       // w0 <= 4 always
    uint32_t b4 = __funnelshift_r(lo, hi, (uint32_t)sh);
    float4 v;
    v.x = (float)( b4        & 1u);
    v.y = (float)((b4 >> 1)  & 1u);
    v.z = (float)((b4 >> 2)  & 1u);
    v.w = (float)((b4 >> 3)  & 1u);
    reinterpret_cast<float4*>(out)[(size_t)n*1024000u + i] = v;
  }
}

// ---------------- launch -----------------------------------------------------
extern "C" void kernel_launch(void* const* d_in, const int* in_sizes, int n_in,
                              void* d_out, int out_size){
  (void)in_sizes; (void)n_in; (void)out_size;
  const float* img = (const float*)d_in[0];
  float* out = (float*)d_out;
  k_all<<<NBLK, NTHR>>>(img, out);
}